// round 7
// baseline (speedup 1.0000x reference)
#include <cuda_runtime.h>
#include <math.h>

#define N 512
#define D 256
#define BT 32
#define NBLK 136              // 16*17/2 triangle of 32x32 tiles
#define MAXP 48               // max positives per anchor (avg ~7)
#define FULL 0xFFFFFFFFu

// __device__ scratch (allocation-free rule)
__device__ float g_alist[N * MAXP];   // d(anchor,positive)+margin, ranked slots
__device__ float g_pS[NBLK];
__device__ float g_pC[NBLK];
__device__ int   g_bar1;              // alist-publish barrier
__device__ int   g_bar2;              // completion counter

__global__ void __launch_bounds__(256)
fused_kernel(const float* __restrict__ x, const int* __restrict__ labels,
             float* __restrict__ out) {
    __shared__ int      lab[N];
    __shared__ unsigned bm[64 * 16];  // per-label 512-bit membership mask
    __shared__ float    As[BT][34];   // [k][m] k-major
    __shared__ float    Bs[BT][34];   // [k][n] k-major
    __shared__ float    s_d[BT][33];  // dist tile
    __shared__ float    sqi[BT], sqj[BT];
    __shared__ int      s_nposR[BT], s_nposC[BT];
    __shared__ float    sred[8], credf[8];
    __shared__ int      s_last;

    const int t = threadIdx.x;        // 0..255
    const int lane = t & 31;
    const int w = t >> 5;             // 0..7

    // triangle decode (bi >= bj)
    int b = blockIdx.x;
    int bi = (int)((sqrtf(8.f * (float)b + 1.f) - 1.f) * 0.5f);
    while ((bi + 1) * (bi + 2) / 2 <= b) bi++;
    while (bi * (bi + 1) / 2 > b) bi--;
    const int bj = b - bi * (bi + 1) / 2;
    const int i0 = bi * BT;
    const int j0 = bj * BT;

    // ---- labels + label bitmask ----
    reinterpret_cast<int2*>(lab)[t] = reinterpret_cast<const int2*>(labels)[t];
    bm[t] = 0u; bm[t + 256] = 0u; bm[t + 512] = 0u; bm[t + 768] = 0u;
    __syncthreads();
    atomicOr(&bm[lab[t]       * 16 + (t >> 5)],        1u << (t & 31));
    atomicOr(&bm[lab[t + 256] * 16 + ((t + 256) >> 5)], 1u << (t & 31));
    __syncthreads();

    // npos for the 64 tile anchors
    if (t < 64) {
        int a = (t < 32) ? (i0 + t) : (j0 + t - 32);
        const unsigned* r = &bm[lab[a] * 16];
        int s = 0;
#pragma unroll
        for (int c = 0; c < 16; c++) s += __popc(r[c]);
        if (t < 32) s_nposR[t] = s - 1; else s_nposC[t - 32] = s - 1;
    }

    // ---- sq norms: warp w handles 8 of the 64 rows ----
#pragma unroll
    for (int rr = 0; rr < 8; rr++) {
        int r = w * 8 + rr;
        int gr = (r < 32) ? (i0 + r) : (j0 + r - 32);
        const float* row = x + gr * D;
        float s = 0.f;
#pragma unroll
        for (int c = 0; c < 8; c++) { float v = row[lane + 32 * c]; s += v * v; }
#pragma unroll
        for (int o = 16; o > 0; o >>= 1) s += __shfl_down_sync(FULL, s, o);
        if (lane == 0) { if (r < 32) sqi[r] = s; else sqj[r - 32] = s; }
    }

    // ---- GEMM (R6 core): 2x2 register tile, k-major smem ----
    const int lr = t >> 3;            // loader row 0..31
    const int lk = (t & 7) * 4;       // loader k offset
    const int tx = t & 15;            // j pair
    const int ty = t >> 4;            // i pair

    float acc00 = 0.f, acc01 = 0.f, acc10 = 0.f, acc11 = 0.f;
    const float* pa = x + (i0 + lr) * D + lk;
    const float* pb = x + (j0 + lr) * D + lk;
    float4 va = *reinterpret_cast<const float4*>(pa);
    float4 vb = *reinterpret_cast<const float4*>(pb);

#pragma unroll
    for (int ch = 0; ch < D / BT; ch++) {
        __syncthreads();
        As[lk + 0][lr] = va.x; As[lk + 1][lr] = va.y;
        As[lk + 2][lr] = va.z; As[lk + 3][lr] = va.w;
        Bs[lk + 0][lr] = vb.x; Bs[lk + 1][lr] = vb.y;
        Bs[lk + 2][lr] = vb.z; Bs[lk + 3][lr] = vb.w;
        __syncthreads();
        if (ch < D / BT - 1) {
            va = *reinterpret_cast<const float4*>(pa + (ch + 1) * BT);
            vb = *reinterpret_cast<const float4*>(pb + (ch + 1) * BT);
        }
#pragma unroll
        for (int k = 0; k < BT; k++) {
            float2 a  = *reinterpret_cast<const float2*>(&As[k][2 * ty]);
            float2 bq = *reinterpret_cast<const float2*>(&Bs[k][2 * tx]);
            acc00 += a.x * bq.x; acc01 += a.x * bq.y;
            acc10 += a.y * bq.x; acc11 += a.y * bq.y;
        }
    }

    // ---- epilogue: s_d tile + scatter positive distances to g_alist ----
    {
        float dv[2][2];
        dv[0][0] = sqrtf(fmaxf(sqi[2*ty]   + sqj[2*tx]   - 2.f * acc00, 1e-16f));
        dv[0][1] = sqrtf(fmaxf(sqi[2*ty]   + sqj[2*tx+1] - 2.f * acc01, 1e-16f));
        dv[1][0] = sqrtf(fmaxf(sqi[2*ty+1] + sqj[2*tx]   - 2.f * acc10, 1e-16f));
        dv[1][1] = sqrtf(fmaxf(sqi[2*ty+1] + sqj[2*tx+1] - 2.f * acc11, 1e-16f));
#pragma unroll
        for (int r = 0; r < 2; r++)
#pragma unroll
            for (int c = 0; c < 2; c++) {
                int ig = i0 + 2 * ty + r;
                int jg = j0 + 2 * tx + c;
                float d = dv[r][c];
                s_d[2 * ty + r][2 * tx + c] = d;
                if (lab[ig] == lab[jg] && ig != jg) {
                    // slot = rank of jg among positives of ig
                    {
                        const unsigned* rm = &bm[lab[ig] * 16];
                        int cj = jg >> 5, s = 0;
                        for (int cc = 0; cc < cj; cc++) s += __popc(rm[cc]);
                        s += __popc(rm[cj] & ((1u << (jg & 31)) - 1u));
                        if (ig < jg) s -= 1;
                        g_alist[ig * MAXP + s] = d + 1.0f;
                    }
                    if (bi != bj) {   // mirror anchor (diag handled by transpose elem)
                        const unsigned* rm = &bm[lab[jg] * 16];
                        int cj = ig >> 5, s = 0;
                        for (int cc = 0; cc < cj; cc++) s += __popc(rm[cc]);
                        s += __popc(rm[cj] & ((1u << (ig & 31)) - 1u));
                        if (jg < ig) s -= 1;
                        g_alist[jg * MAXP + s] = d + 1.0f;
                    }
                }
            }
    }

    // ---- grid barrier: publish g_alist ----
    __threadfence();                   // every thread releases its STGs
    __syncthreads();
    if (t == 0) {
        atomicAdd(&g_bar1, 1);
        volatile int* p = &g_bar1;
        while (*p < NBLK) { }
    }
    __syncthreads();

    // ---- hinge: warp w owns rows/cols 4w..4w+3 ----
    float sum = 0.f;
    int cnt = 0;
#pragma unroll
    for (int rr = 0; rr < 4; rr++) {
        int r = w * 4 + rr;
        int A = i0 + r;
        int np = s_nposR[r];
        if (np > 0) {
            float areg = (lane < np && lane < 32)
                       ? __ldcg(&g_alist[A * MAXP + lane]) : 0.f;
            bool neg = (lab[j0 + lane] != lab[A]);
            float dvv = s_d[r][lane];
            int npc = (np < 32) ? np : 32;
            for (int p = 0; p < npc; p++) {
                float aa = __shfl_sync(FULL, areg, p);
                float v = aa - dvv;
                if (neg) { if (v > 0.f) sum += v; if (v > 1e-16f) cnt++; }
            }
            for (int p = 32; p < np; p++) {      // overflow path (rare)
                float aa = __ldcg(&g_alist[A * MAXP + p]);
                float v = aa - dvv;
                if (neg) { if (v > 0.f) sum += v; if (v > 1e-16f) cnt++; }
            }
        }
    }
    if (bi != bj) {
#pragma unroll
        for (int rr = 0; rr < 4; rr++) {
            int c = w * 4 + rr;
            int A = j0 + c;
            int np = s_nposC[c];
            if (np > 0) {
                float areg = (lane < np && lane < 32)
                           ? __ldcg(&g_alist[A * MAXP + lane]) : 0.f;
                bool neg = (lab[i0 + lane] != lab[A]);
                float dvv = s_d[lane][c];
                int npc = (np < 32) ? np : 32;
                for (int p = 0; p < npc; p++) {
                    float aa = __shfl_sync(FULL, areg, p);
                    float v = aa - dvv;
                    if (neg) { if (v > 0.f) sum += v; if (v > 1e-16f) cnt++; }
                }
                for (int p = 32; p < np; p++) {
                    float aa = __ldcg(&g_alist[A * MAXP + p]);
                    float v = aa - dvv;
                    if (neg) { if (v > 0.f) sum += v; if (v > 1e-16f) cnt++; }
                }
            }
        }
    }

    // ---- block reduce -> partials -> last-block final reduce ----
#pragma unroll
    for (int o = 16; o > 0; o >>= 1) {
        sum += __shfl_down_sync(FULL, sum, o);
        cnt += __shfl_down_sync(FULL, cnt, o);
    }
    if (lane == 0) { sred[w] = sum; credf[w] = (float)cnt; }
    __syncthreads();
    if (t == 0) {
        float s = 0.f, c = 0.f;
#pragma unroll
        for (int k = 0; k < 8; k++) { s += sred[k]; c += credf[k]; }
        g_pS[blockIdx.x] = s;
        g_pC[blockIdx.x] = c;
        __threadfence();
        int old = atomicAdd(&g_bar2, 1);
        s_last = (old == NBLK - 1) ? 1 : 0;
    }
    __syncthreads();

    if (s_last) {
        __threadfence();
        float s = (t < NBLK) ? __ldcg(&g_pS[t]) : 0.f;
        float c = (t < NBLK) ? __ldcg(&g_pC[t]) : 0.f;
#pragma unroll
        for (int o = 16; o > 0; o >>= 1) {
            s += __shfl_down_sync(FULL, s, o);
            c += __shfl_down_sync(FULL, c, o);
        }
        if (lane == 0) { sred[w] = s; credf[w] = c; }
        __syncthreads();
        if (t == 0) {
            float S = 0.f, C = 0.f;
#pragma unroll
            for (int k = 0; k < 8; k++) { S += sred[k]; C += credf[k]; }
            out[0] = S / (C + 1e-16f);
            g_bar1 = 0;               // reset for next graph replay
            g_bar2 = 0;
        }
    }
}

// ---------------------------------------------------------------------------
extern "C" void kernel_launch(void* const* d_in, const int* in_sizes, int n_in,
                              void* d_out, int out_size) {
    const float* x      = (const float*)d_in[0];   // (512, 256) float32
    const int*   labels = (const int*)d_in[1];     // (512,) int32
    float* out = (float*)d_out;

    fused_kernel<<<NBLK, 256>>>(x, labels, out);
}

// round 8
// speedup vs baseline: 1.2503x; 1.2503x over previous
#include <cuda_runtime.h>
#include <math.h>

#define N 512
#define D 256
#define BT 32
#define NBLK 136              // 16*17/2 triangle of 32x32 tiles
#define NCLS 64
#define MAXP 64
#define FULL 0xFFFFFFFFu

// __device__ scratch (allocation-free rule)
__device__ float g_alist[N * MAXP];   // d(anchor,positive)+margin, ranked
__device__ int   g_npos[N];
__device__ float g_pS[NBLK];
__device__ float g_pC[NBLK];
__device__ int   g_done = 0;

// ---------------------------------------------------------------------------
// Kernel A: positive-pair distances, one block per class (64 blocks).
// Warp-per-dot over class members (~8): sq norms then all pairs.
// ---------------------------------------------------------------------------
__global__ void __launch_bounds__(256)
alist_kernel(const float* __restrict__ x, const int* __restrict__ labels) {
    __shared__ int   lab[N];
    __shared__ int   midx[MAXP];
    __shared__ float sqm[MAXP];
    __shared__ int   segc[16];
    __shared__ int   s_m;

    const int t = threadIdx.x;        // 0..255
    const int lane = t & 31;
    const int w = t >> 5;             // 0..7
    const int cls = blockIdx.x;

    reinterpret_cast<int2*>(lab)[t] = reinterpret_cast<const int2*>(labels)[t];
    __syncthreads();

    // ordered compaction of class members (positions ascending)
    bool m0 = (lab[t] == cls);
    bool m1 = (lab[t + 256] == cls);
    unsigned b0 = __ballot_sync(FULL, m0);
    unsigned b1 = __ballot_sync(FULL, m1);
    if (lane == 0) { segc[w] = __popc(b0); segc[8 + w] = __popc(b1); }
    __syncthreads();
    if (m0) {
        int off = 0;
        for (int s = 0; s < w; s++) off += segc[s];
        off += __popc(b0 & ((1u << lane) - 1u));
        if (off < MAXP) midx[off] = t;
    }
    if (m1) {
        int off = 0;
        for (int s = 0; s < 8 + w; s++) off += segc[s];
        off += __popc(b1 & ((1u << lane) - 1u));
        if (off < MAXP) midx[off] = t + 256;
    }
    if (t == 0) {
        int tot = 0;
        for (int s = 0; s < 16; s++) tot += segc[s];
        s_m = (tot > MAXP) ? MAXP : tot;
    }
    __syncthreads();
    const int m = s_m;

    // sq norms of members (warp-per-member)
    for (int p = w; p < m; p += 8) {
        const float* row = x + midx[p] * D;
        float s = 0.f;
#pragma unroll
        for (int c = 0; c < 8; c++) { float v = row[lane + 32 * c]; s += v * v; }
#pragma unroll
        for (int o = 16; o > 0; o >>= 1) s += __shfl_down_sync(FULL, s, o);
        if (lane == 0) sqm[p] = s;
    }
    __syncthreads();

    // all member pairs p<q (warp-per-pair)
    const int T = m * (m - 1) / 2;
    for (int tt = w; tt < T; tt += 8) {
        int rem = tt, p = 0;
        while (rem >= m - 1 - p) { rem -= m - 1 - p; p++; }
        int q = p + 1 + rem;
        const float* xi = x + midx[p] * D;
        const float* xj = x + midx[q] * D;
        float dot = 0.f;
#pragma unroll
        for (int c = 0; c < 8; c++) dot += xi[lane + 32 * c] * xj[lane + 32 * c];
#pragma unroll
        for (int o = 16; o > 0; o >>= 1) dot += __shfl_down_sync(FULL, dot, o);
        if (lane == 0) {
            float a = sqrtf(fmaxf(sqm[p] + sqm[q] - 2.f * dot, 1e-16f)) + 1.0f;
            // ranked slots: positives of midx[p] are members q'!=p in order
            g_alist[midx[p] * MAXP + (q - 1)] = a;
            g_alist[midx[q] * MAXP + p]       = a;
        }
    }
    if (t < m) g_npos[midx[t]] = m - 1;
}

// ---------------------------------------------------------------------------
// Kernel B: dist GEMM (register d, never stored) + fused hinge + final reduce.
// 136 triangle blocks, 256 threads, 2x2 register tile.
// ---------------------------------------------------------------------------
__global__ void __launch_bounds__(256)
disthinge_kernel(const float* __restrict__ x, const int* __restrict__ labels,
                 float* __restrict__ out) {
    __shared__ float As[BT][34];      // [k][m]
    __shared__ float Bs[BT][34];      // [k][n]
    __shared__ int   lab[N];
    __shared__ float a_sm[64][33];    // staged a-lists for the 64 tile anchors
    __shared__ int   s_np[64];
    __shared__ float sqi[BT], sqj[BT];
    __shared__ float sred[8], cred[8];
    __shared__ int   s_last;

    const int t = threadIdx.x;        // 0..255
    const int lane = t & 31;
    const int w = t >> 5;

    // triangle decode (bi >= bj)
    int b = blockIdx.x;
    int bi = (int)((sqrtf(8.f * (float)b + 1.f) - 1.f) * 0.5f);
    while ((bi + 1) * (bi + 2) / 2 <= b) bi++;
    while (bi * (bi + 1) / 2 > b) bi--;
    const int bj = b - bi * (bi + 1) / 2;
    const int i0 = bi * BT;
    const int j0 = bj * BT;

    // labels + a-list staging (L2 reads; latency overlapped by sq phase)
    reinterpret_cast<int2*>(lab)[t] = reinterpret_cast<const int2*>(labels)[t];
    if (t < 64) {
        int A = (t < 32) ? (i0 + t) : (j0 + t - 32);
        s_np[t] = g_npos[A];
    }
#pragma unroll
    for (int s = 0; s < 8; s++) {
        int idx = t + s * 256;        // 0..2047
        int al = idx >> 5;            // 0..63
        int p  = idx & 31;
        int A = (al < 32) ? (i0 + al) : (j0 + al - 32);
        a_sm[al][p] = g_alist[A * MAXP + p];   // unread slots harmless
    }

    // sq norms: warp w handles 8 of the 64 rows
#pragma unroll
    for (int rr = 0; rr < 8; rr++) {
        int r = w * 8 + rr;
        int gr = (r < 32) ? (i0 + r) : (j0 + r - 32);
        const float* row = x + gr * D;
        float s = 0.f;
#pragma unroll
        for (int c = 0; c < 8; c++) { float v = row[lane + 32 * c]; s += v * v; }
#pragma unroll
        for (int o = 16; o > 0; o >>= 1) s += __shfl_down_sync(FULL, s, o);
        if (lane == 0) { if (r < 32) sqi[r] = s; else sqj[r - 32] = s; }
    }

    // GEMM: 2x2 register tile, k-major smem (R6 core)
    const int lr = t >> 3;
    const int lk = (t & 7) * 4;
    const int tx = t & 15;
    const int ty = t >> 4;

    float acc00 = 0.f, acc01 = 0.f, acc10 = 0.f, acc11 = 0.f;
    const float* pa = x + (i0 + lr) * D + lk;
    const float* pb = x + (j0 + lr) * D + lk;
    float4 va = *reinterpret_cast<const float4*>(pa);
    float4 vb = *reinterpret_cast<const float4*>(pb);

#pragma unroll
    for (int ch = 0; ch < D / BT; ch++) {
        __syncthreads();
        As[lk + 0][lr] = va.x; As[lk + 1][lr] = va.y;
        As[lk + 2][lr] = va.z; As[lk + 3][lr] = va.w;
        Bs[lk + 0][lr] = vb.x; Bs[lk + 1][lr] = vb.y;
        Bs[lk + 2][lr] = vb.z; Bs[lk + 3][lr] = vb.w;
        __syncthreads();
        if (ch < D / BT - 1) {
            va = *reinterpret_cast<const float4*>(pa + (ch + 1) * BT);
            vb = *reinterpret_cast<const float4*>(pb + (ch + 1) * BT);
        }
#pragma unroll
        for (int k = 0; k < BT; k++) {
            float2 a  = *reinterpret_cast<const float2*>(&As[k][2 * ty]);
            float2 bq = *reinterpret_cast<const float2*>(&Bs[k][2 * tx]);
            acc00 += a.x * bq.x; acc01 += a.x * bq.y;
            acc10 += a.y * bq.x; acc11 += a.y * bq.y;
        }
    }

    // distances in registers (never stored)
    float dv[2][2];
    dv[0][0] = sqrtf(fmaxf(sqi[2*ty]   + sqj[2*tx]   - 2.f * acc00, 1e-16f));
    dv[0][1] = sqrtf(fmaxf(sqi[2*ty]   + sqj[2*tx+1] - 2.f * acc01, 1e-16f));
    dv[1][0] = sqrtf(fmaxf(sqi[2*ty+1] + sqj[2*tx]   - 2.f * acc10, 1e-16f));
    dv[1][1] = sqrtf(fmaxf(sqi[2*ty+1] + sqj[2*tx+1] - 2.f * acc11, 1e-16f));

    // ---- fused hinge ----
    const int labA0 = lab[i0 + 2 * ty], labA1 = lab[i0 + 2 * ty + 1];
    const int labC0 = lab[j0 + 2 * tx], labC1 = lab[j0 + 2 * tx + 1];
    float sum = 0.f, cntf = 0.f;

    // row pass: anchors = this thread's 2 rows; negatives = its 2 cols
#pragma unroll
    for (int r = 0; r < 2; r++) {
        const int al = 2 * ty + r;
        const int la = (r == 0) ? labA0 : labA1;
        const bool n0 = (labC0 != la);
        const bool n1 = (labC1 != la);
        const int np = s_np[al];
        const int npc = (np < 32) ? np : 32;
        for (int p = 0; p < npc; p++) {
            float a = a_sm[al][p];
            float v0 = a - dv[r][0];
            float v1 = a - dv[r][1];
            if (n0 && v0 > 1e-16f) { sum += v0; cntf += 1.f; }
            if (n1 && v1 > 1e-16f) { sum += v1; cntf += 1.f; }
        }
        for (int p = 32; p < np; p++) {          // overflow (never in practice)
            float a = __ldcg(&g_alist[(i0 + al) * MAXP + p]);
            float v0 = a - dv[r][0];
            float v1 = a - dv[r][1];
            if (n0 && v0 > 1e-16f) { sum += v0; cntf += 1.f; }
            if (n1 && v1 > 1e-16f) { sum += v1; cntf += 1.f; }
        }
    }
    // col pass (anchors = the 2 cols; negatives = the 2 rows); off-diag only
    if (bi != bj) {
#pragma unroll
        for (int cc = 0; cc < 2; cc++) {
            const int al = 32 + 2 * tx + cc;
            const int la = (cc == 0) ? labC0 : labC1;
            const bool n0 = (labA0 != la);
            const bool n1 = (labA1 != la);
            const int np = s_np[al];
            const int npc = (np < 32) ? np : 32;
            for (int p = 0; p < npc; p++) {
                float a = a_sm[al][p];
                float v0 = a - dv[0][cc];
                float v1 = a - dv[1][cc];
                if (n0 && v0 > 1e-16f) { sum += v0; cntf += 1.f; }
                if (n1 && v1 > 1e-16f) { sum += v1; cntf += 1.f; }
            }
            for (int p = 32; p < np; p++) {
                float a = __ldcg(&g_alist[(j0 + 2 * tx + cc) * MAXP + p]);
                float v0 = a - dv[0][cc];
                float v1 = a - dv[1][cc];
                if (n0 && v0 > 1e-16f) { sum += v0; cntf += 1.f; }
                if (n1 && v1 > 1e-16f) { sum += v1; cntf += 1.f; }
            }
        }
    }

    // ---- block reduce -> partial; last block does final reduce ----
#pragma unroll
    for (int o = 16; o > 0; o >>= 1) {
        sum  += __shfl_down_sync(FULL, sum, o);
        cntf += __shfl_down_sync(FULL, cntf, o);
    }
    if (lane == 0) { sred[w] = sum; cred[w] = cntf; }
    __syncthreads();
    if (t == 0) {
        float s = 0.f, c = 0.f;
#pragma unroll
        for (int k = 0; k < 8; k++) { s += sred[k]; c += cred[k]; }
        g_pS[blockIdx.x] = s;
        g_pC[blockIdx.x] = c;
        __threadfence();
        int old = atomicAdd(&g_done, 1);
        s_last = (old == NBLK - 1) ? 1 : 0;
    }
    __syncthreads();

    if (s_last) {
        __threadfence();
        float s = (t < NBLK) ? __ldcg(&g_pS[t]) : 0.f;
        float c = (t < NBLK) ? __ldcg(&g_pC[t]) : 0.f;
#pragma unroll
        for (int o = 16; o > 0; o >>= 1) {
            s += __shfl_down_sync(FULL, s, o);
            c += __shfl_down_sync(FULL, c, o);
        }
        if (lane == 0) { sred[w] = s; cred[w] = c; }
        __syncthreads();
        if (t == 0) {
            float S = 0.f, C = 0.f;
#pragma unroll
            for (int k = 0; k < 8; k++) { S += sred[k]; C += cred[k]; }
            out[0] = S / (C + 1e-16f);
            g_done = 0;               // reset for next graph replay
        }
    }
}

// ---------------------------------------------------------------------------
extern "C" void kernel_launch(void* const* d_in, const int* in_sizes, int n_in,
                              void* d_out, int out_size) {
    const float* x      = (const float*)d_in[0];   // (512, 256) float32
    const int*   labels = (const int*)d_in[1];     // (512,) int32
    float* out = (float*)d_out;

    alist_kernel<<<NCLS, 256>>>(x, labels);
    disthinge_kernel<<<NBLK, 256>>>(x, labels, out);
}

// round 9
// speedup vs baseline: 1.4661x; 1.1726x over previous
#include <cuda_runtime.h>
#include <math.h>

#define N 512
#define D 256
#define BT 32
#define NBLK_D 136            // 16*17/2 triangle of 32x32 tiles
#define NBLK_T 512
#define MAXP 32               // a-list slots per anchor
#define FULL 0xFFFFFFFFu

// __device__ scratch (allocation-free rule; zero-init at module load)
__device__ float g_dist[N * N];
__device__ float g_alist[N * MAXP];   // d(anchor,positive)+margin, rank slots
__device__ int   g_npos[N];
__device__ float g_psum[NBLK_T];
__device__ float g_pcnt[NBLK_T];
__device__ int   g_done = 0;

// ---------------------------------------------------------------------------
// Kernel 1: fused sq-norms + symmetric distances + positive a-list scatter.
// 136 triangle blocks, 256 threads, 2x2 register tile, k-major smem.
// Mirror tile written coalesced via s_d transpose staging.
// ---------------------------------------------------------------------------
__global__ void __launch_bounds__(256)
dist_kernel(const float* __restrict__ x, const int* __restrict__ labels) {
    __shared__ float    As[BT][34];   // [k][m]
    __shared__ float    Bs[BT][34];   // [k][n]
    __shared__ float    s_d[BT][33];  // dist tile (row i, col j)
    __shared__ int      lab[N];
    __shared__ unsigned bm[64 * 16];  // per-label 512-bit membership mask
    __shared__ float    sqi[BT], sqj[BT];

    const int t = threadIdx.x;        // 0..255
    const int lane = t & 31;
    const int w = t >> 5;             // 0..7

    // triangle decode (bi >= bj)
    int b = blockIdx.x;
    int bi = (int)((sqrtf(8.f * (float)b + 1.f) - 1.f) * 0.5f);
    while ((bi + 1) * (bi + 2) / 2 <= b) bi++;
    while (bi * (bi + 1) / 2 > b) bi--;
    const int bj = b - bi * (bi + 1) / 2;
    const int i0 = bi * BT;
    const int j0 = bj * BT;

    // labels + label bitmask
    reinterpret_cast<int2*>(lab)[t] = reinterpret_cast<const int2*>(labels)[t];
    bm[t] = 0u; bm[t + 256] = 0u; bm[t + 512] = 0u; bm[t + 768] = 0u;
    __syncthreads();
    atomicOr(&bm[lab[t]       * 16 + (t >> 5)],         1u << (t & 31));
    atomicOr(&bm[lab[t + 256] * 16 + ((t + 256) >> 5)], 1u << (t & 31));
    __syncthreads();

    // npos for the 64 tile anchors -> g_npos (duplicate same-value writes ok)
    if (t < 64) {
        int A = (t < 32) ? (i0 + t) : (j0 + t - 32);
        const unsigned* r = &bm[lab[A] * 16];
        int s = 0;
#pragma unroll
        for (int c = 0; c < 16; c++) s += __popc(r[c]);
        g_npos[A] = s - 1;
    }

    // sq norms: warp w handles 8 of the 64 rows
#pragma unroll
    for (int rr = 0; rr < 8; rr++) {
        int r = w * 8 + rr;
        int gr = (r < 32) ? (i0 + r) : (j0 + r - 32);
        const float* row = x + gr * D;
        float s = 0.f;
#pragma unroll
        for (int c = 0; c < 8; c++) { float v = row[lane + 32 * c]; s += v * v; }
#pragma unroll
        for (int o = 16; o > 0; o >>= 1) s += __shfl_down_sync(FULL, s, o);
        if (lane == 0) { if (r < 32) sqi[r] = s; else sqj[r - 32] = s; }
    }

    // GEMM: 2x2 register tile, k-major smem
    const int lr = t >> 3;
    const int lk = (t & 7) * 4;
    const int tx = t & 15;
    const int ty = t >> 4;

    float acc00 = 0.f, acc01 = 0.f, acc10 = 0.f, acc11 = 0.f;
    const float* pa = x + (i0 + lr) * D + lk;
    const float* pb = x + (j0 + lr) * D + lk;
    float4 va = *reinterpret_cast<const float4*>(pa);
    float4 vb = *reinterpret_cast<const float4*>(pb);

#pragma unroll
    for (int ch = 0; ch < D / BT; ch++) {
        __syncthreads();
        As[lk + 0][lr] = va.x; As[lk + 1][lr] = va.y;
        As[lk + 2][lr] = va.z; As[lk + 3][lr] = va.w;
        Bs[lk + 0][lr] = vb.x; Bs[lk + 1][lr] = vb.y;
        Bs[lk + 2][lr] = vb.z; Bs[lk + 3][lr] = vb.w;
        __syncthreads();
        if (ch < D / BT - 1) {
            va = *reinterpret_cast<const float4*>(pa + (ch + 1) * BT);
            vb = *reinterpret_cast<const float4*>(pb + (ch + 1) * BT);
        }
#pragma unroll
        for (int k = 0; k < BT; k++) {
            float2 a  = *reinterpret_cast<const float2*>(&As[k][2 * ty]);
            float2 bq = *reinterpret_cast<const float2*>(&Bs[k][2 * tx]);
            acc00 += a.x * bq.x; acc01 += a.x * bq.y;
            acc10 += a.y * bq.x; acc11 += a.y * bq.y;
        }
    }

    // epilogue: distances -> s_d, main-tile write, positive a-list scatter
    {
        float dv[2][2];
        dv[0][0] = sqrtf(fmaxf(sqi[2*ty]   + sqj[2*tx]   - 2.f * acc00, 1e-16f));
        dv[0][1] = sqrtf(fmaxf(sqi[2*ty]   + sqj[2*tx+1] - 2.f * acc01, 1e-16f));
        dv[1][0] = sqrtf(fmaxf(sqi[2*ty+1] + sqj[2*tx]   - 2.f * acc10, 1e-16f));
        dv[1][1] = sqrtf(fmaxf(sqi[2*ty+1] + sqj[2*tx+1] - 2.f * acc11, 1e-16f));

        const int ig = i0 + 2 * ty;
        const int jg = j0 + 2 * tx;
        *reinterpret_cast<float2*>(g_dist + (ig    ) * N + jg) =
            make_float2(dv[0][0], dv[0][1]);
        *reinterpret_cast<float2*>(g_dist + (ig + 1) * N + jg) =
            make_float2(dv[1][0], dv[1][1]);

#pragma unroll
        for (int r = 0; r < 2; r++)
#pragma unroll
            for (int c = 0; c < 2; c++) {
                s_d[2 * ty + r][2 * tx + c] = dv[r][c];
                int I = ig + r, J = jg + c;
                if (lab[I] == lab[J] && I != J) {
                    {   // slot = rank of J among positives of I
                        const unsigned* rm = &bm[lab[I] * 16];
                        int cj = J >> 5, s = 0;
                        for (int cc = 0; cc < cj; cc++) s += __popc(rm[cc]);
                        s += __popc(rm[cj] & ((1u << (J & 31)) - 1u));
                        if (I < J) s -= 1;
                        if (s < MAXP) g_alist[I * MAXP + s] = dv[r][c] + 1.0f;
                    }
                    if (bi != bj) {   // mirror anchor
                        const unsigned* rm = &bm[lab[J] * 16];
                        int cj = I >> 5, s = 0;
                        for (int cc = 0; cc < cj; cc++) s += __popc(rm[cc]);
                        s += __popc(rm[cj] & ((1u << (I & 31)) - 1u));
                        if (J < I) s -= 1;
                        if (s < MAXP) g_alist[J * MAXP + s] = dv[r][c] + 1.0f;
                    }
                }
            }
    }
    __syncthreads();

    // mirror tile write, coalesced: warp w writes 4 rows of the transpose
    if (bi != bj) {
#pragma unroll
        for (int rr = 0; rr < 4; rr++) {
            int jr = w * 4 + rr;                   // 0..31
            g_dist[(j0 + jr) * N + i0 + lane] = s_d[lane][jr];
        }
    }
}

// ---------------------------------------------------------------------------
// Kernel 2: triplet reduction, 512 blocks x 512 threads, unrolled hinge.
// ---------------------------------------------------------------------------
__global__ void __launch_bounds__(512)
triplet_kernel(const int* __restrict__ labels, float* __restrict__ out) {
    __shared__ float a_sm[MAXP];
    __shared__ int   s_np;
    __shared__ float sred[16];
    __shared__ float cred[16];
    __shared__ int   s_last;

    const int i = blockIdx.x;         // anchor
    const int t = threadIdx.x;        // 0..511
    const int lane = t & 31;
    const int w = t >> 5;             // 0..15

    if (t < MAXP) a_sm[t] = g_alist[i * MAXP + t];
    if (t == MAXP) s_np = g_npos[i];

    const int li = __ldg(&labels[i]);            // broadcast
    const bool neg = (__ldg(&labels[t]) != li);  // t==i -> same label -> false
    const float d = g_dist[i * N + t];
    __syncthreads();

    float s0 = 0.f, s1 = 0.f, c0 = 0.f, c1 = 0.f;
#pragma unroll
    for (int p = 0; p < 16; p += 2) {
        float v0 = a_sm[p]     - d;
        float v1 = a_sm[p + 1] - d;
        s0 += fmaxf(v0, 0.f);
        s1 += fmaxf(v1, 0.f);
        if (v0 > 1e-16f) c0 += 1.f;
        if (v1 > 1e-16f) c1 += 1.f;
    }
    if (s_np > 16) {                  // uniform branch per block (rare)
#pragma unroll
        for (int p = 16; p < MAXP; p += 2) {
            float v0 = a_sm[p]     - d;
            float v1 = a_sm[p + 1] - d;
            s0 += fmaxf(v0, 0.f);
            s1 += fmaxf(v1, 0.f);
            if (v0 > 1e-16f) c0 += 1.f;
            if (v1 > 1e-16f) c1 += 1.f;
        }
    }
    float sum = neg ? (s0 + s1) : 0.f;
    float cnt = neg ? (c0 + c1) : 0.f;

    // deterministic block reduction (16 warps)
#pragma unroll
    for (int o = 16; o > 0; o >>= 1) {
        sum += __shfl_down_sync(FULL, sum, o);
        cnt += __shfl_down_sync(FULL, cnt, o);
    }
    if (lane == 0) { sred[w] = sum; cred[w] = cnt; }
    __syncthreads();
    if (t == 0) {
        float s = 0.f, c = 0.f;
#pragma unroll
        for (int k = 0; k < 16; k++) { s += sred[k]; c += cred[k]; }
        g_psum[i] = s;
        g_pcnt[i] = c;
        __threadfence();
        int old = atomicAdd(&g_done, 1);
        s_last = (old == NBLK_T - 1) ? 1 : 0;
    }
    __syncthreads();

    if (s_last) {                     // final reduction over 512 partials
        __threadfence();
        float s = __ldcg(&g_psum[t]);
        float c = __ldcg(&g_pcnt[t]);
#pragma unroll
        for (int o = 16; o > 0; o >>= 1) {
            s += __shfl_down_sync(FULL, s, o);
            c += __shfl_down_sync(FULL, c, o);
        }
        if (lane == 0) { sred[w] = s; cred[w] = c; }
        __syncthreads();
        if (t == 0) {
            float S = 0.f, C = 0.f;
#pragma unroll
            for (int k = 0; k < 16; k++) { S += sred[k]; C += cred[k]; }
            out[0] = S / (C + 1e-16f);
            g_done = 0;               // reset for next graph replay
        }
    }
}

// ---------------------------------------------------------------------------
extern "C" void kernel_launch(void* const* d_in, const int* in_sizes, int n_in,
                              void* d_out, int out_size) {
    const float* x      = (const float*)d_in[0];   // (512, 256) float32
    const int*   labels = (const int*)d_in[1];     // (512,) int32
    float* out = (float*)d_out;

    dist_kernel<<<NBLK_D, 256>>>(x, labels);
    triplet_kernel<<<NBLK_T, 512>>>(labels, out);
}